// round 2
// baseline (speedup 1.0000x reference)
#include <cuda_runtime.h>
#include <cstdint>

#define B_ 32
#define P_ 24
#define S_ 48
#define H_ 512
#define F_ 64
#define D_ 576    // H + F
#define G4_ 2048  // 4*H
#define O_ 16
#define EPS_ 1e-5f
#define NMASK_ (B_ * P_ * S_)

// ---------------- scratch (device globals, no allocation) ----------------
__device__ float g_seq[P_ * B_ * D_];     // rep, layout [t][b][d]
__device__ float g_Gx[P_ * B_ * G4_];     // input projection + bias, [t][b][n]
__device__ float g_h[2][B_ * H_];         // ping-pong hidden
__device__ float g_c[2][B_ * H_];         // ping-pong cell
__device__ float g_hb[B_ * H_];           // backward first-step hidden
__device__ int   g_mask_mode;             // 0=int32, 1=float32, 2=uint8

__device__ __forceinline__ float sigf(float x) { return 1.f / (1.f + expf(-x)); }
__device__ __forceinline__ float wred(float v) {
    #pragma unroll
    for (int o = 16; o; o >>= 1) v += __shfl_xor_sync(0xffffffffu, v, o);
    return v;
}
__device__ __forceinline__ int num_valid(const int* lens) {
    int nv = 0;
    while (nv < B_ && lens[nv] == P_) nv++;
    return nv;
}
__device__ __forceinline__ int read_mask(const void* xm, int idx, int mode) {
    if (mode == 0) return ((const int*)xm)[idx] != 0;
    if (mode == 1) return ((const float*)xm)[idx] != 0.f;
    return ((const unsigned char*)xm)[idx] != 0;
}

// ---------------- K0: probe x_mask dtype ----------------
// Reads only the first NMASK_ bytes (safe under uint8/int32/float32 hypotheses).
__global__ __launch_bounds__(256) void probe_mask_kernel(const unsigned char* __restrict__ xm)
{
    __shared__ int s_nz1, s_nz23;
    if (threadIdx.x == 0) { s_nz1 = 0; s_nz23 = 0; }
    __syncthreads();
    int ln1 = 0, ln23 = 0;
    for (int i = threadIdx.x; i < NMASK_; i += 256) {
        unsigned char v = xm[i];
        int m = i & 3;
        if (v && m == 1) ln1 = 1;
        if (v && m != 0) ln23 = 1;
    }
    if (ln1)  atomicOr(&s_nz1, 1);
    if (ln23) atomicOr(&s_nz23, 1);
    __syncthreads();
    if (threadIdx.x == 0)
        g_mask_mode = (s_nz23 == 0) ? 0 : (s_nz1 == 0 ? 1 : 2);
}

// ---------------- K1: embedding gather + attention + rep ----------------
// one CTA per (b,p); only active where lens[b]==P
__global__ __launch_bounds__(256) void attn_rep_kernel(
    const int* __restrict__ x, const void* __restrict__ xmask,
    const float* __restrict__ xfeat, const int* __restrict__ lens,
    const float* __restrict__ emb, const float* __restrict__ wattn,
    const float* __restrict__ battn)
{
    int bp = blockIdx.x;
    int b = bp / P_;
    if (lens[b] != P_) return;
    int p = bp % P_;

    extern __shared__ char smraw[];
    float* E     = (float*)smraw;          // S*H
    float* wv    = E + S_ * H_;            // H
    float* sc    = wv + H_;                // S
    float* alpha = sc + S_;                // S
    int*   toks  = (int*)(alpha + S_);     // S
    int*   msk   = toks + S_;              // S

    int tid = threadIdx.x;
    int mode = g_mask_mode;
    if (tid < S_) {
        toks[tid] = x[bp * S_ + tid];
        msk[tid]  = read_mask(xmask, bp * S_ + tid, mode);
    }
    for (int i = tid; i < H_; i += 256) wv[i] = wattn[i];
    __syncthreads();

    // gather embedding rows into smem (float4)
    const float4* emb4 = (const float4*)emb;
    float4* E4 = (float4*)E;
    for (int idx = tid; idx < S_ * (H_ / 4); idx += 256) {
        int row = idx >> 7;       // / (H/4=128)
        int c4  = idx & 127;
        E4[idx] = emb4[(size_t)toks[row] * (H_ / 4) + c4];
    }
    __syncthreads();

    int warp = tid >> 5, lane = tid & 31;
    // attention scores
    for (int s = warp; s < S_; s += 8) {
        float acc = 0.f;
        for (int k = lane; k < H_; k += 32) acc += E[s * H_ + k] * wv[k];
        acc = wred(acc);
        if (lane == 0) sc[s] = msk[s] ? -1e30f : (acc + battn[0]);
    }
    __syncthreads();

    // softmax over S by warp 0
    if (warp == 0) {
        float v0 = sc[lane];
        float v1 = (lane < 16) ? sc[32 + lane] : -3e38f;
        float m = fmaxf(v0, v1);
        #pragma unroll
        for (int o = 16; o; o >>= 1) m = fmaxf(m, __shfl_xor_sync(0xffffffffu, m, o));
        float e0 = expf(v0 - m);
        float e1 = (lane < 16) ? expf(v1 - m) : 0.f;
        float ssum = wred(e0 + e1);
        float inv = 1.f / ssum;
        alpha[lane] = msk[lane] ? 0.f : e0 * inv;
        if (lane < 16) alpha[32 + lane] = msk[32 + lane] ? 0.f : e1 * inv;
    }
    __syncthreads();

    float* outrow = &g_seq[(p * B_ + b) * D_];
    for (int h = tid; h < H_; h += 256) {
        float acc = 0.f;
        #pragma unroll 8
        for (int s = 0; s < S_; s++) acc += alpha[s] * E[s * H_ + h];
        outrow[h] = acc;
    }
    if (tid < F_) {
        float acc = 0.f;
        for (int s = 0; s < S_; s++)
            if (!msk[s]) acc += xfeat[((size_t)bp * S_ + s) * F_ + tid];
        outrow[H_ + tid] = acc;
    }
}

// ---------------- K2: Gx[t][b][n] = seq[t][b]·Wih_f[n] + bih+bhh ----------------
// one warp per (t, n); only valid b
__global__ __launch_bounds__(256) void gx_kernel(
    const int* __restrict__ lens, const float* __restrict__ Wih,
    const float* __restrict__ bih, const float* __restrict__ bhh)
{
    int gw = (blockIdx.x * blockDim.x + threadIdx.x) >> 5;
    int lane = threadIdx.x & 31;
    int t = gw >> 11;         // / 2048
    int n = gw & 2047;
    int nv = num_valid(lens);
    const float* wrow = Wih + (size_t)n * D_;
    for (int b0 = 0; b0 < nv; b0 += 4) {
        int rem = nv - b0;
        float a0 = 0, a1 = 0, a2 = 0, a3 = 0;
        for (int kk = lane; kk < D_; kk += 32) {
            float w = wrow[kk];
            a0 += w * g_seq[(t * B_ + b0) * D_ + kk];
            if (rem > 1) a1 += w * g_seq[(t * B_ + b0 + 1) * D_ + kk];
            if (rem > 2) a2 += w * g_seq[(t * B_ + b0 + 2) * D_ + kk];
            if (rem > 3) a3 += w * g_seq[(t * B_ + b0 + 3) * D_ + kk];
        }
        a0 = wred(a0); a1 = wred(a1); a2 = wred(a2); a3 = wred(a3);
        if (lane == 0) {
            float bias = bih[n] + bhh[n];
            g_Gx[((size_t)t * B_ + b0) * G4_ + n] = a0 + bias;
            if (rem > 1) g_Gx[((size_t)t * B_ + b0 + 1) * G4_ + n] = a1 + bias;
            if (rem > 2) g_Gx[((size_t)t * B_ + b0 + 2) * G4_ + n] = a2 + bias;
            if (rem > 3) g_Gx[((size_t)t * B_ + b0 + 3) * G4_ + n] = a3 + bias;
        }
    }
}

// ---------------- K3: one forward LSTM step ----------------
// one warp per hidden unit j; computes all 4 gate dot-products over Whh
__global__ __launch_bounds__(256) void lstm_step_kernel(
    const int* __restrict__ lens, const float* __restrict__ Whh, int t)
{
    int j = (blockIdx.x * blockDim.x + threadIdx.x) >> 5;
    int lane = threadIdx.x & 31;
    if (j >= H_) return;
    int nv = num_valid(lens);

    const float* hprev = g_h[t & 1];
    const float* cprev = g_c[t & 1];
    float* hn = g_h[(t + 1) & 1];
    float* cn = g_c[(t + 1) & 1];
    const float* wi = Whh + (size_t)j * H_;
    const float* wf = Whh + (size_t)(H_ + j) * H_;
    const float* wg = Whh + (size_t)(2 * H_ + j) * H_;
    const float* wo = Whh + (size_t)(3 * H_ + j) * H_;

    for (int b0 = 0; b0 < nv; b0 += 2) {
        bool has1 = (b0 + 1) < nv;
        float ai0 = 0, af0 = 0, ag0 = 0, ao0 = 0;
        float ai1 = 0, af1 = 0, ag1 = 0, ao1 = 0;
        if (t > 0) {
            #pragma unroll 4
            for (int kk = lane; kk < H_; kk += 32) {
                float w0 = wi[kk], w1 = wf[kk], w2 = wg[kk], w3 = wo[kk];
                float h0 = hprev[b0 * H_ + kk];
                ai0 += w0 * h0; af0 += w1 * h0; ag0 += w2 * h0; ao0 += w3 * h0;
                if (has1) {
                    float h1 = hprev[(b0 + 1) * H_ + kk];
                    ai1 += w0 * h1; af1 += w1 * h1; ag1 += w2 * h1; ao1 += w3 * h1;
                }
            }
            ai0 = wred(ai0); af0 = wred(af0); ag0 = wred(ag0); ao0 = wred(ao0);
            if (has1) { ai1 = wred(ai1); af1 = wred(af1); ag1 = wred(ag1); ao1 = wred(ao1); }
        }
        if (lane == 0) {
            {
                const float* gx = &g_Gx[((size_t)t * B_ + b0) * G4_];
                float gi = ai0 + gx[j], gf = af0 + gx[H_ + j];
                float gg = ag0 + gx[2 * H_ + j], go = ao0 + gx[3 * H_ + j];
                float cp = (t > 0) ? cprev[b0 * H_ + j] : 0.f;
                float cnew = sigf(gf) * cp + sigf(gi) * tanhf(gg);
                cn[b0 * H_ + j] = cnew;
                hn[b0 * H_ + j] = sigf(go) * tanhf(cnew);
            }
            if (has1) {
                const float* gx = &g_Gx[((size_t)t * B_ + b0 + 1) * G4_];
                float gi = ai1 + gx[j], gf = af1 + gx[H_ + j];
                float gg = ag1 + gx[2 * H_ + j], go = ao1 + gx[3 * H_ + j];
                float cp = (t > 0) ? cprev[(b0 + 1) * H_ + j] : 0.f;
                float cnew = sigf(gf) * cp + sigf(gi) * tanhf(gg);
                cn[(b0 + 1) * H_ + j] = cnew;
                hn[(b0 + 1) * H_ + j] = sigf(go) * tanhf(cnew);
            }
        }
    }
}

// ---------------- K4: single backward LSTM step (h0=c0=0) ----------------
__global__ __launch_bounds__(256) void bwd_kernel(
    const int* __restrict__ lens, const float* __restrict__ Wih,
    const float* __restrict__ bih, const float* __restrict__ bhh)
{
    int j = (blockIdx.x * blockDim.x + threadIdx.x) >> 5;
    int lane = threadIdx.x & 31;
    if (j >= H_) return;
    int nv = num_valid(lens);

    const float* wi = Wih + (size_t)j * D_;
    const float* wf = Wih + (size_t)(H_ + j) * D_;
    const float* wg = Wih + (size_t)(2 * H_ + j) * D_;
    const float* wo = Wih + (size_t)(3 * H_ + j) * D_;

    for (int b = 0; b < nv; b++) {
        // rev_in[0,b] = seq[lens[b]-1, b] = seq[P-1, b] for valid b
        const float* xr = &g_seq[((P_ - 1) * B_ + b) * D_];
        float ai = 0, af = 0, ag = 0, ao = 0;
        #pragma unroll 4
        for (int kk = lane; kk < D_; kk += 32) {
            float xv = xr[kk];
            ai += wi[kk] * xv; af += wf[kk] * xv;
            ag += wg[kk] * xv; ao += wo[kk] * xv;
        }
        ai = wred(ai); af = wred(af); ag = wred(ag); ao = wred(ao);
        if (lane == 0) {
            float bi = bih[j] + bhh[j];
            float bf = bih[H_ + j] + bhh[H_ + j];
            float bg = bih[2 * H_ + j] + bhh[2 * H_ + j];
            float bo = bih[3 * H_ + j] + bhh[3 * H_ + j];
            float cnew = sigf(ai + bi) * tanhf(ag + bg);   // c_prev = 0
            g_hb[b * H_ + j] = sigf(ao + bo) * tanhf(cnew);
        }
    }
}

// ---------------- K5: FC + batch-LN + relu + log_softmax(axis=0) ----------------
__global__ __launch_bounds__(512) void final_kernel(
    const int* __restrict__ lens, const float* __restrict__ Wfc,
    const float* __restrict__ bfc, const float* __restrict__ gamma,
    const float* __restrict__ beta, float* __restrict__ out)
{
    __shared__ float ys[B_ * O_];
    __shared__ float mean_s[O_], inv_s[O_], lse_s[O_];
    int tid = threadIdx.x;
    int i = tid >> 4;     // row 0..31
    int o = tid & 15;     // col 0..15
    int nv = num_valid(lens);
    const float* hf = g_h[P_ & 1];   // after 24 steps, final h lives in g_h[0]

    // y[i][o] = bfc[o] + sum_j z[i][j]*Wfc[o][j],  z[i][j] = last[j%32][i*32 + j/32]
    float acc = bfc[o];
    for (int b = 0; b < nv; b++) {
        #pragma unroll 8
        for (int jq = 0; jq < 32; jq++) {
            int u = i * 32 + jq;
            float lv = (u < H_) ? hf[b * H_ + u] : g_hb[b * H_ + (u - H_)];
            acc += lv * Wfc[o * (2 * H_) + jq * 32 + b];
        }
    }
    ys[i * O_ + o] = acc;
    __syncthreads();

    if (tid < O_) {
        float m = 0.f;
        for (int r = 0; r < B_; r++) m += ys[r * O_ + tid];
        m *= (1.f / B_);
        float v = 0.f;
        for (int r = 0; r < B_; r++) { float d = ys[r * O_ + tid] - m; v += d * d; }
        v *= (1.f / B_);
        mean_s[tid] = m;
        inv_s[tid] = 1.f / sqrtf(v + EPS_);
    }
    __syncthreads();

    float yn = gamma[o] * (ys[i * O_ + o] - mean_s[o]) * inv_s[o] + beta[o];
    yn = fmaxf(yn, 0.f);
    ys[i * O_ + o] = yn;
    __syncthreads();

    if (tid < O_) {
        float mx = -3e38f;
        for (int r = 0; r < B_; r++) mx = fmaxf(mx, ys[r * O_ + tid]);
        float ss = 0.f;
        for (int r = 0; r < B_; r++) ss += expf(ys[r * O_ + tid] - mx);
        lse_s[tid] = logf(ss) + mx;
    }
    __syncthreads();

    out[i * O_ + o] = ys[i * O_ + o] - lse_s[o];
}

// ---------------- launcher ----------------
extern "C" void kernel_launch(void* const* d_in, const int* in_sizes, int n_in,
                              void* d_out, int out_size)
{
    const int*           x      = (const int*)d_in[0];
    const void*          xm     = d_in[1];
    const float*         xf     = (const float*)d_in[2];
    const int*           lens   = (const int*)d_in[3];
    // d_in[4]=clause, d_in[5]=cls : unused
    const float* emb    = (const float*)d_in[6];
    const float* wattn  = (const float*)d_in[7];
    const float* battn  = (const float*)d_in[8];
    const float* Wih_f  = (const float*)d_in[9];
    const float* Whh_f  = (const float*)d_in[10];
    const float* bih_f  = (const float*)d_in[11];
    const float* bhh_f  = (const float*)d_in[12];
    const float* Wih_b  = (const float*)d_in[13];
    const float* Whh_b  = (const float*)d_in[14];  (void)Whh_b;
    const float* bih_b  = (const float*)d_in[15];
    const float* bhh_b  = (const float*)d_in[16];
    const float* Wfc    = (const float*)d_in[17];
    const float* bfc    = (const float*)d_in[18];
    const float* gamma  = (const float*)d_in[19];
    const float* beta   = (const float*)d_in[20];
    float* out = (float*)d_out;

    const int K1_SMEM = (S_ * H_ + H_ + 2 * S_) * 4 + 2 * S_ * 4;  // ~101 KB
    cudaFuncSetAttribute(attn_rep_kernel,
                         cudaFuncAttributeMaxDynamicSharedMemorySize, K1_SMEM);

    probe_mask_kernel<<<1, 256>>>((const unsigned char*)xm);
    attn_rep_kernel<<<B_ * P_, 256, K1_SMEM>>>(x, xm, xf, lens, emb, wattn, battn);
    gx_kernel<<<(P_ * G4_) / 8, 256>>>(lens, Wih_f, bih_f, bhh_f);
    bwd_kernel<<<(H_ * 32) / 256, 256>>>(lens, Wih_b, bih_b, bhh_b);
    for (int t = 0; t < P_; t++)
        lstm_step_kernel<<<(H_ * 32) / 256, 256>>>(lens, Whh_f, t);
    final_kernel<<<1, 512>>>(lens, Wfc, bfc, gamma, beta, out);
}

// round 3
// speedup vs baseline: 1.5073x; 1.5073x over previous
#include <cuda_runtime.h>
#include <cstdint>

#define B_ 32
#define P_ 24
#define S_ 48
#define H_ 512
#define F_ 64
#define D_ 576    // H + F
#define G4_ 2048  // 4*H
#define O_ 16
#define EPS_ 1e-5f
#define NMASK_ (B_ * P_ * S_)
#define NCTA_ 64

// ---------------- scratch (device globals, no allocation) ----------------
__device__ float g_seq[P_ * B_ * D_];     // rep, layout [t][b][d]
__device__ float g_Gx[P_ * B_ * G4_];     // input projection + bias, [t][b][n]
__device__ float g_h[2][B_ * H_];         // ping-pong hidden
__device__ float g_c[2][B_ * H_];         // ping-pong cell
__device__ float g_hb[B_ * H_];           // backward first-step hidden
__device__ int   g_mask_mode;             // 0=int32, 1=float32, 2=uint8
__device__ int   g_bar;                   // grid barrier counter (reset by probe)

__device__ __forceinline__ float sigf(float x) { return 1.f / (1.f + expf(-x)); }
__device__ __forceinline__ float wred(float v) {
    #pragma unroll
    for (int o = 16; o; o >>= 1) v += __shfl_xor_sync(0xffffffffu, v, o);
    return v;
}
__device__ __forceinline__ int num_valid(const int* lens) {
    int nv = 0;
    while (nv < B_ && lens[nv] == P_) nv++;
    return nv;
}
__device__ __forceinline__ int read_mask(const void* xm, int idx, int mode) {
    if (mode == 0) return ((const int*)xm)[idx] != 0;
    if (mode == 1) return ((const float*)xm)[idx] != 0.f;
    return ((const unsigned char*)xm)[idx] != 0;
}

// ---------------- K0: probe x_mask dtype + reset grid barrier ----------------
__global__ __launch_bounds__(256) void probe_mask_kernel(const unsigned char* __restrict__ xm)
{
    __shared__ int s_nz1, s_nz23;
    if (threadIdx.x == 0) { s_nz1 = 0; s_nz23 = 0; g_bar = 0; }
    __syncthreads();
    int ln1 = 0, ln23 = 0;
    for (int i = threadIdx.x; i < NMASK_; i += 256) {
        unsigned char v = xm[i];
        int m = i & 3;
        if (v && m == 1) ln1 = 1;
        if (v && m != 0) ln23 = 1;
    }
    if (ln1)  atomicOr(&s_nz1, 1);
    if (ln23) atomicOr(&s_nz23, 1);
    __syncthreads();
    if (threadIdx.x == 0)
        g_mask_mode = (s_nz23 == 0) ? 0 : (s_nz1 == 0 ? 1 : 2);
}

// ---------------- K1: embedding gather + attention + rep ----------------
__global__ __launch_bounds__(256) void attn_rep_kernel(
    const int* __restrict__ x, const void* __restrict__ xmask,
    const float* __restrict__ xfeat, const int* __restrict__ lens,
    const float* __restrict__ emb, const float* __restrict__ wattn,
    const float* __restrict__ battn)
{
    int bp = blockIdx.x;
    int b = bp / P_;
    if (lens[b] != P_) return;
    int p = bp % P_;

    extern __shared__ char smraw[];
    float* E     = (float*)smraw;          // S*H
    float* wv    = E + S_ * H_;            // H
    float* sc    = wv + H_;                // S
    float* alpha = sc + S_;                // S
    int*   toks  = (int*)(alpha + S_);     // S
    int*   msk   = toks + S_;              // S

    int tid = threadIdx.x;
    int mode = g_mask_mode;
    if (tid < S_) {
        toks[tid] = x[bp * S_ + tid];
        msk[tid]  = read_mask(xmask, bp * S_ + tid, mode);
    }
    for (int i = tid; i < H_; i += 256) wv[i] = wattn[i];
    __syncthreads();

    const float4* emb4 = (const float4*)emb;
    float4* E4 = (float4*)E;
    for (int idx = tid; idx < S_ * (H_ / 4); idx += 256) {
        int row = idx >> 7;
        int c4  = idx & 127;
        E4[idx] = emb4[(size_t)toks[row] * (H_ / 4) + c4];
    }
    __syncthreads();

    int warp = tid >> 5, lane = tid & 31;
    for (int s = warp; s < S_; s += 8) {
        float acc = 0.f;
        for (int k = lane; k < H_; k += 32) acc += E[s * H_ + k] * wv[k];
        acc = wred(acc);
        if (lane == 0) sc[s] = msk[s] ? -1e30f : (acc + battn[0]);
    }
    __syncthreads();

    if (warp == 0) {
        float v0 = sc[lane];
        float v1 = (lane < 16) ? sc[32 + lane] : -3e38f;
        float m = fmaxf(v0, v1);
        #pragma unroll
        for (int o = 16; o; o >>= 1) m = fmaxf(m, __shfl_xor_sync(0xffffffffu, m, o));
        float e0 = expf(v0 - m);
        float e1 = (lane < 16) ? expf(v1 - m) : 0.f;
        float ssum = wred(e0 + e1);
        float inv = 1.f / ssum;
        alpha[lane] = msk[lane] ? 0.f : e0 * inv;
        if (lane < 16) alpha[32 + lane] = msk[32 + lane] ? 0.f : e1 * inv;
    }
    __syncthreads();

    float* outrow = &g_seq[(p * B_ + b) * D_];
    for (int h = tid; h < H_; h += 256) {
        float acc = 0.f;
        #pragma unroll 8
        for (int s = 0; s < S_; s++) acc += alpha[s] * E[s * H_ + h];
        outrow[h] = acc;
    }
    if (tid < F_) {
        float acc = 0.f;
        for (int s = 0; s < S_; s++)
            if (!msk[s]) acc += xfeat[((size_t)bp * S_ + s) * F_ + tid];
        outrow[H_ + tid] = acc;
    }
}

// ---------------- K2: Gx[t][b][n] = seq[t][b]·Wih_f[n] + bih+bhh ----------------
// 64 CTAs; CTA k owns n in [k*32, k*32+32). seq staged in SMEM per b-chunk of 2;
// each warp holds the 576-float weight row in registers across all (t,b).
__global__ __launch_bounds__(256) void gx_kernel(
    const int* __restrict__ lens, const float* __restrict__ Wih,
    const float* __restrict__ bih, const float* __restrict__ bhh)
{
    extern __shared__ float sseq[];   // [24][2][576]
    int tid = threadIdx.x, warp = tid >> 5, lane = tid & 31;
    int nv = num_valid(lens);

    for (int b0 = 0; b0 < nv; b0 += 2) {
        int bc = (nv - b0) < 2 ? (nv - b0) : 2;
        // stage seq chunk
        for (int q = tid; q < P_ * bc * 144; q += 256) {
            int t  = q / (bc * 144);
            int r  = q - t * (bc * 144);
            int bb = r / 144;
            int c4 = r - bb * 144;
            ((float4*)sseq)[(t * 2 + bb) * 144 + c4] =
                ((const float4*)g_seq)[((size_t)(t * B_ + b0 + bb)) * 144 + c4];
        }
        __syncthreads();

        #pragma unroll
        for (int nn = 0; nn < 4; nn++) {
            int n = blockIdx.x * 32 + warp * 4 + nn;
            float wreg[18];
            #pragma unroll
            for (int i = 0; i < 18; i++) wreg[i] = Wih[(size_t)n * D_ + lane + 32 * i];
            float bias = bih[n] + bhh[n];
            for (int t = 0; t < P_; t++) {
                for (int bb = 0; bb < bc; bb++) {
                    const float* sp = &sseq[(t * 2 + bb) * D_];
                    float acc = 0.f;
                    #pragma unroll
                    for (int i = 0; i < 18; i++) acc += wreg[i] * sp[lane + 32 * i];
                    acc = wred(acc);
                    if (lane == 0)
                        g_Gx[((size_t)t * B_ + b0 + bb) * G4_ + n] = acc + bias;
                }
            }
        }
        __syncthreads();
    }
}

// ---------------- K3: fused 24-step forward LSTM (persistent, grid barrier) ----
// 64 CTAs; CTA k owns hidden units j in [k*8, k*8+8); 32 Whh rows cached in SMEM.
__global__ __launch_bounds__(256) void lstm_fused_kernel(
    const int* __restrict__ lens, const float* __restrict__ Whh)
{
    extern __shared__ float sm[];
    float* sW   = sm;               // [4][8][512] = 16384 floats
    float* hbuf = sm + 32 * H_;     // [4][512]
    int k = blockIdx.x, tid = threadIdx.x, warp = tid >> 5, lane = tid & 31;

    // cache this CTA's 32 Whh rows (gate-major: [gate][jj][512])
    const float4* W4 = (const float4*)Whh;
    float4* sW4 = (float4*)sW;
    for (int q = tid; q < 4096; q += 256) {
        int rl = q >> 7;           // local row 0..31
        int c4 = q & 127;
        int g  = rl >> 3, jj = rl & 7;
        sW4[q] = W4[(size_t)(g * H_ + k * 8 + jj) * 128 + c4];
    }
    int nv = num_valid(lens);
    __syncthreads();

    int j = k * 8 + warp;
    const float* w0 = &sW[(0 * 8 + warp) * H_];
    const float* w1 = &sW[(1 * 8 + warp) * H_];
    const float* w2 = &sW[(2 * 8 + warp) * H_];
    const float* w3 = &sW[(3 * 8 + warp) * H_];

    for (int t = 0; t < P_; t++) {
        const float* hsrc = g_h[t & 1];
        const float* csrc = g_c[t & 1];
        float* hdst = g_h[(t + 1) & 1];
        float* cdst = g_c[(t + 1) & 1];

        for (int b0 = 0; b0 < nv; b0 += 4) {
            int bc = (nv - b0) < 4 ? (nv - b0) : 4;
            if (t > 0) {
                // stage h_prev chunk; __ldcg: other CTAs wrote it (L1 not coherent)
                for (int q = tid; q < bc * H_; q += 256)
                    hbuf[q] = __ldcg(&hsrc[b0 * H_ + q]);
            }
            __syncthreads();
            for (int bb = 0; bb < bc; bb++) {
                float ai = 0, af = 0, ag = 0, ao = 0;
                if (t > 0) {
                    const float* hp = &hbuf[bb * H_];
                    #pragma unroll
                    for (int i = 0; i < 16; i++) {
                        int kk = lane + 32 * i;
                        float h = hp[kk];
                        ai += w0[kk] * h; af += w1[kk] * h;
                        ag += w2[kk] * h; ao += w3[kk] * h;
                    }
                    ai = wred(ai); af = wred(af); ag = wred(ag); ao = wred(ao);
                }
                if (lane == 0) {
                    int b = b0 + bb;
                    const float* gx = &g_Gx[((size_t)t * B_ + b) * G4_];
                    float gi = ai + gx[j];
                    float gf = af + gx[H_ + j];
                    float gg = ag + gx[2 * H_ + j];
                    float go = ao + gx[3 * H_ + j];
                    float cp = (t > 0) ? csrc[b * H_ + j] : 0.f;  // own-warp write only
                    float cn = sigf(gf) * cp + sigf(gi) * tanhf(gg);
                    cdst[b * H_ + j] = cn;
                    hdst[b * H_ + j] = sigf(go) * tanhf(cn);
                }
            }
            __syncthreads();
        }

        // grid barrier (monotonic counter, reset each replay by probe kernel)
        __threadfence();
        __syncthreads();
        if (tid == 0) {
            atomicAdd(&g_bar, 1);
            int target = NCTA_ * (t + 1);
            while (*(volatile int*)&g_bar < target) { }
        }
        __syncthreads();
    }
}

// ---------------- K4: single backward LSTM step (h0=c0=0), float4 ----------------
__global__ __launch_bounds__(256) void bwd_kernel(
    const int* __restrict__ lens, const float* __restrict__ Wih,
    const float* __restrict__ bih, const float* __restrict__ bhh)
{
    int j = (blockIdx.x * blockDim.x + threadIdx.x) >> 5;
    int lane = threadIdx.x & 31;
    if (j >= H_) return;
    int nv = num_valid(lens);

    const float4* wi4 = (const float4*)(Wih + (size_t)j * D_);
    const float4* wf4 = (const float4*)(Wih + (size_t)(H_ + j) * D_);
    const float4* wg4 = (const float4*)(Wih + (size_t)(2 * H_ + j) * D_);
    const float4* wo4 = (const float4*)(Wih + (size_t)(3 * H_ + j) * D_);

    for (int b = 0; b < nv; b++) {
        const float4* xr4 = (const float4*)&g_seq[((P_ - 1) * B_ + b) * D_];
        float ai = 0, af = 0, ag = 0, ao = 0;
        #pragma unroll
        for (int u = 0; u < 5; u++) {
            int i = lane + 32 * u;
            if (i < 144) {
                float4 xv = xr4[i];
                float4 a = wi4[i]; ai += a.x*xv.x + a.y*xv.y + a.z*xv.z + a.w*xv.w;
                float4 bq = wf4[i]; af += bq.x*xv.x + bq.y*xv.y + bq.z*xv.z + bq.w*xv.w;
                float4 c = wg4[i]; ag += c.x*xv.x + c.y*xv.y + c.z*xv.z + c.w*xv.w;
                float4 d = wo4[i]; ao += d.x*xv.x + d.y*xv.y + d.z*xv.z + d.w*xv.w;
            }
        }
        ai = wred(ai); af = wred(af); ag = wred(ag); ao = wred(ao);
        if (lane == 0) {
            float bi = bih[j] + bhh[j];
            float bg = bih[2 * H_ + j] + bhh[2 * H_ + j];
            float bo = bih[3 * H_ + j] + bhh[3 * H_ + j];
            float cnew = sigf(ai + bi) * tanhf(ag + bg);   // c_prev = 0
            g_hb[b * H_ + j] = sigf(ao + bo) * tanhf(cnew);
        }
    }
}

// ---------------- K5: FC + batch-LN + relu + log_softmax(axis=0) ----------------
__global__ __launch_bounds__(512) void final_kernel(
    const int* __restrict__ lens, const float* __restrict__ Wfc,
    const float* __restrict__ bfc, const float* __restrict__ gamma,
    const float* __restrict__ beta, float* __restrict__ out)
{
    __shared__ float ys[B_ * O_];
    __shared__ float mean_s[O_], inv_s[O_], lse_s[O_];
    int tid = threadIdx.x;
    int i = tid >> 4;     // row 0..31
    int o = tid & 15;     // col 0..15
    int nv = num_valid(lens);
    const float* hf = g_h[P_ & 1];   // after 24 steps, final h in g_h[0]

    // y[i][o] = bfc[o] + sum_j z[i][j]*Wfc[o][j],  z[i][j] = last[j%32][i*32 + j/32]
    float acc = bfc[o];
    for (int b = 0; b < nv; b++) {
        #pragma unroll 8
        for (int jq = 0; jq < 32; jq++) {
            int u = i * 32 + jq;
            float lv = (u < H_) ? hf[b * H_ + u] : g_hb[b * H_ + (u - H_)];
            acc += lv * Wfc[o * (2 * H_) + jq * 32 + b];
        }
    }
    ys[i * O_ + o] = acc;
    __syncthreads();

    if (tid < O_) {
        float m = 0.f;
        for (int r = 0; r < B_; r++) m += ys[r * O_ + tid];
        m *= (1.f / B_);
        float v = 0.f;
        for (int r = 0; r < B_; r++) { float d = ys[r * O_ + tid] - m; v += d * d; }
        v *= (1.f / B_);
        mean_s[tid] = m;
        inv_s[tid] = 1.f / sqrtf(v + EPS_);
    }
    __syncthreads();

    float yn = gamma[o] * (ys[i * O_ + o] - mean_s[o]) * inv_s[o] + beta[o];
    yn = fmaxf(yn, 0.f);
    ys[i * O_ + o] = yn;
    __syncthreads();

    if (tid < O_) {
        float mx = -3e38f;
        for (int r = 0; r < B_; r++) mx = fmaxf(mx, ys[r * O_ + tid]);
        float ss = 0.f;
        for (int r = 0; r < B_; r++) ss += expf(ys[r * O_ + tid] - mx);
        lse_s[tid] = logf(ss) + mx;
    }
    __syncthreads();

    out[i * O_ + o] = ys[i * O_ + o] - lse_s[o];
}

// ---------------- launcher ----------------
extern "C" void kernel_launch(void* const* d_in, const int* in_sizes, int n_in,
                              void* d_out, int out_size)
{
    const int*  x    = (const int*)d_in[0];
    const void* xm   = d_in[1];
    const float* xf  = (const float*)d_in[2];
    const int*  lens = (const int*)d_in[3];
    const float* emb    = (const float*)d_in[6];
    const float* wattn  = (const float*)d_in[7];
    const float* battn  = (const float*)d_in[8];
    const float* Wih_f  = (const float*)d_in[9];
    const float* Whh_f  = (const float*)d_in[10];
    const float* bih_f  = (const float*)d_in[11];
    const float* bhh_f  = (const float*)d_in[12];
    const float* Wih_b  = (const float*)d_in[13];
    const float* bih_b  = (const float*)d_in[15];
    const float* bhh_b  = (const float*)d_in[16];
    const float* Wfc    = (const float*)d_in[17];
    const float* bfc    = (const float*)d_in[18];
    const float* gamma  = (const float*)d_in[19];
    const float* beta   = (const float*)d_in[20];
    float* out = (float*)d_out;

    const int K1_SMEM   = (S_ * H_ + H_ + 2 * S_) * 4 + 2 * S_ * 4;   // ~101 KB
    const int GX_SMEM   = P_ * 2 * D_ * 4;                             // 110592
    const int LSTM_SMEM = (32 * H_ + 4 * H_) * 4;                      // 73728
    cudaFuncSetAttribute(attn_rep_kernel,
                         cudaFuncAttributeMaxDynamicSharedMemorySize, K1_SMEM);
    cudaFuncSetAttribute(gx_kernel,
                         cudaFuncAttributeMaxDynamicSharedMemorySize, GX_SMEM);
    cudaFuncSetAttribute(lstm_fused_kernel,
                         cudaFuncAttributeMaxDynamicSharedMemorySize, LSTM_SMEM);

    probe_mask_kernel<<<1, 256>>>((const unsigned char*)xm);
    attn_rep_kernel<<<B_ * P_, 256, K1_SMEM>>>(x, xm, xf, lens, emb, wattn, battn);
    gx_kernel<<<NCTA_, 256, GX_SMEM>>>(lens, Wih_f, bih_f, bhh_f);
    bwd_kernel<<<(H_ * 32) / 256, 256>>>(lens, Wih_b, bih_b, bhh_b);
    lstm_fused_kernel<<<NCTA_, 256, LSTM_SMEM>>>(lens, Whh_f);
    final_kernel<<<1, 512>>>(lens, Wfc, bfc, gamma, beta, out);
}

// round 4
// speedup vs baseline: 1.7027x; 1.1296x over previous
#include <cuda_runtime.h>
#include <cstdint>

#define B_ 32
#define P_ 24
#define S_ 48
#define H_ 512
#define F_ 64
#define D_ 576    // H + F
#define G4_ 2048  // 4*H
#define O_ 16
#define EPS_ 1e-5f
#define NCTA_ 64

// ---------------- scratch (device globals, no allocation) ----------------
__device__ float g_seq[P_ * B_ * D_];     // rep, layout [t][b][d]
__device__ float g_Gx[P_ * B_ * G4_];     // input projection + bias, [t][b][n]
__device__ float g_h[2][B_ * H_];         // ping-pong hidden
__device__ float g_c[2][B_ * H_];         // ping-pong cell
__device__ float g_hb[B_ * H_];           // backward first-step hidden
__device__ int   g_bar;                   // grid barrier counter (reset in gxbwd)

__device__ __forceinline__ float sigf(float x) { return 1.f / (1.f + expf(-x)); }
__device__ __forceinline__ float wred(float v) {
    #pragma unroll
    for (int o = 16; o; o >>= 1) v += __shfl_xor_sync(0xffffffffu, v, o);
    return v;
}
__device__ __forceinline__ int num_valid(const int* lens) {
    int nv = 0;
    while (nv < B_ && lens[nv] == P_) nv++;
    return nv;
}

// ---------------- K1: embedding gather + attention + rep ----------------
__global__ __launch_bounds__(512) void attn_rep_kernel(
    const int* __restrict__ x, const int* __restrict__ xmask,
    const float* __restrict__ xfeat, const int* __restrict__ lens,
    const float* __restrict__ emb, const float* __restrict__ wattn,
    const float* __restrict__ battn)
{
    int bp = blockIdx.x;
    int b = bp / P_;
    if (lens[b] != P_) return;
    int p = bp % P_;

    extern __shared__ char smraw[];
    float* E     = (float*)smraw;          // S*H
    float* wv    = E + S_ * H_;            // H
    float* sc    = wv + H_;                // S
    float* alpha = sc + S_;                // S
    int*   toks  = (int*)(alpha + S_);     // S
    int*   msk   = toks + S_;              // S

    int tid = threadIdx.x;
    if (tid < S_) {
        toks[tid] = x[bp * S_ + tid];
        msk[tid]  = (xmask[bp * S_ + tid] != 0);  // works for int32 AND float32
    }
    for (int i = tid; i < H_; i += 512) wv[i] = wattn[i];
    __syncthreads();

    const float4* emb4 = (const float4*)emb;
    float4* E4 = (float4*)E;
    for (int idx = tid; idx < S_ * (H_ / 4); idx += 512) {
        int row = idx >> 7;
        int c4  = idx & 127;
        E4[idx] = emb4[(size_t)toks[row] * (H_ / 4) + c4];
    }
    __syncthreads();

    int warp = tid >> 5, lane = tid & 31;
    for (int s = warp; s < S_; s += 16) {
        float acc = 0.f;
        for (int k = lane; k < H_; k += 32) acc += E[s * H_ + k] * wv[k];
        acc = wred(acc);
        if (lane == 0) sc[s] = msk[s] ? -1e30f : (acc + battn[0]);
    }
    __syncthreads();

    if (warp == 0) {
        float v0 = sc[lane];
        float v1 = (lane < 16) ? sc[32 + lane] : -3e38f;
        float m = fmaxf(v0, v1);
        #pragma unroll
        for (int o = 16; o; o >>= 1) m = fmaxf(m, __shfl_xor_sync(0xffffffffu, m, o));
        float e0 = expf(v0 - m);
        float e1 = (lane < 16) ? expf(v1 - m) : 0.f;
        float ssum = wred(e0 + e1);
        float inv = 1.f / ssum;
        alpha[lane] = msk[lane] ? 0.f : e0 * inv;
        if (lane < 16) alpha[32 + lane] = msk[32 + lane] ? 0.f : e1 * inv;
    }
    __syncthreads();

    float* outrow = &g_seq[(p * B_ + b) * D_];
    for (int h = tid; h < H_; h += 512) {
        float acc = 0.f;
        #pragma unroll 8
        for (int s = 0; s < S_; s++) acc += alpha[s] * E[s * H_ + h];
        outrow[h] = acc;
    }
    if (tid < F_) {
        float acc = 0.f;
        for (int s = 0; s < S_; s++)
            if (!msk[s]) acc += xfeat[((size_t)bp * S_ + s) * F_ + tid];
        outrow[H_ + tid] = acc;
    }
}

// ---------------- K2: fused Gx projection (CTAs 0..63) + backward step (64..127)
__global__ __launch_bounds__(256) void gxbwd_kernel(
    const int* __restrict__ lens,
    const float* __restrict__ Wih_f, const float* __restrict__ bih_f,
    const float* __restrict__ bhh_f,
    const float* __restrict__ Wih_b, const float* __restrict__ bih_b,
    const float* __restrict__ bhh_b)
{
    int tid = threadIdx.x, warp = tid >> 5, lane = tid & 31;
    int nv = num_valid(lens);
    if (tid == 0 && blockIdx.x == 0) g_bar = 0;   // reset grid barrier for lstm

    if (blockIdx.x < NCTA_) {
        // ---- Gx path ----
        extern __shared__ float sseq[];   // [24][2][576]
        for (int b0 = 0; b0 < nv; b0 += 2) {
            int bc = (nv - b0) < 2 ? (nv - b0) : 2;
            for (int q = tid; q < P_ * bc * 144; q += 256) {
                int t  = q / (bc * 144);
                int r  = q - t * (bc * 144);
                int bb = r / 144;
                int c4 = r - bb * 144;
                ((float4*)sseq)[(t * 2 + bb) * 144 + c4] =
                    ((const float4*)g_seq)[((size_t)(t * B_ + b0 + bb)) * 144 + c4];
            }
            __syncthreads();

            #pragma unroll
            for (int nn = 0; nn < 4; nn++) {
                int n = blockIdx.x * 32 + warp * 4 + nn;
                float wreg[18];
                #pragma unroll
                for (int i = 0; i < 18; i++) wreg[i] = Wih_f[(size_t)n * D_ + lane + 32 * i];
                float bias = bih_f[n] + bhh_f[n];
                for (int t = 0; t < P_; t++) {
                    for (int bb = 0; bb < bc; bb++) {
                        const float* sp = &sseq[(t * 2 + bb) * D_];
                        float acc = 0.f;
                        #pragma unroll
                        for (int i = 0; i < 18; i++) acc += wreg[i] * sp[lane + 32 * i];
                        acc = wred(acc);
                        if (lane == 0)
                            g_Gx[((size_t)t * B_ + b0 + bb) * G4_ + n] = acc + bias;
                    }
                }
            }
            __syncthreads();
        }
    } else {
        // ---- backward single-step path ----
        int j = (blockIdx.x - NCTA_) * 8 + warp;
        const float4* wi4 = (const float4*)(Wih_b + (size_t)j * D_);
        const float4* wf4 = (const float4*)(Wih_b + (size_t)(H_ + j) * D_);
        const float4* wg4 = (const float4*)(Wih_b + (size_t)(2 * H_ + j) * D_);
        const float4* wo4 = (const float4*)(Wih_b + (size_t)(3 * H_ + j) * D_);

        for (int b = 0; b < nv; b++) {
            const float4* xr4 = (const float4*)&g_seq[((P_ - 1) * B_ + b) * D_];
            float ai = 0, af = 0, ag = 0, ao = 0;
            #pragma unroll
            for (int u = 0; u < 5; u++) {
                int i = lane + 32 * u;
                if (i < 144) {
                    float4 xv = xr4[i];
                    float4 a = wi4[i]; ai += a.x*xv.x + a.y*xv.y + a.z*xv.z + a.w*xv.w;
                    float4 bq = wf4[i]; af += bq.x*xv.x + bq.y*xv.y + bq.z*xv.z + bq.w*xv.w;
                    float4 c = wg4[i]; ag += c.x*xv.x + c.y*xv.y + c.z*xv.z + c.w*xv.w;
                    float4 d = wo4[i]; ao += d.x*xv.x + d.y*xv.y + d.z*xv.z + d.w*xv.w;
                }
            }
            ai = wred(ai); ag = wred(ag); ao = wred(ao);
            if (lane == 0) {
                float bi = bih_b[j] + bhh_b[j];
                float bg = bih_b[2 * H_ + j] + bhh_b[2 * H_ + j];
                float bo = bih_b[3 * H_ + j] + bhh_b[3 * H_ + j];
                float cnew = sigf(ai + bi) * tanhf(ag + bg);   // c_prev = 0
                g_hb[b * H_ + j] = sigf(ao + bo) * tanhf(cnew);
            }
        }
    }
}

// ---------------- K3: fused 24-step LSTM + final head (persistent, grid barrier)
__global__ __launch_bounds__(256) void lstm_fused_kernel(
    const int* __restrict__ lens, const float* __restrict__ Whh,
    const float* __restrict__ Wfc, const float* __restrict__ bfc,
    const float* __restrict__ gamma, const float* __restrict__ beta,
    float* __restrict__ out)
{
    extern __shared__ float sm[];
    float* sW   = sm;               // [4][8][512] = 16384 floats
    float* hbuf = sm + 32 * H_;     // [4][512]
    int k = blockIdx.x, tid = threadIdx.x, warp = tid >> 5, lane = tid & 31;

    const float4* W4 = (const float4*)Whh;
    float4* sW4 = (float4*)sW;
    for (int q = tid; q < 4096; q += 256) {
        int rl = q >> 7;           // local row 0..31
        int c4 = q & 127;
        int g  = rl >> 3, jj = rl & 7;
        sW4[q] = W4[(size_t)(g * H_ + k * 8 + jj) * 128 + c4];
    }
    int nv = num_valid(lens);
    __syncthreads();

    int j = k * 8 + warp;
    const float* w0 = &sW[(0 * 8 + warp) * H_];
    const float* w1 = &sW[(1 * 8 + warp) * H_];
    const float* w2 = &sW[(2 * 8 + warp) * H_];
    const float* w3 = &sW[(3 * 8 + warp) * H_];

    for (int t = 0; t < P_; t++) {
        const float* hsrc = g_h[t & 1];
        const float* csrc = g_c[t & 1];
        float* hdst = g_h[(t + 1) & 1];
        float* cdst = g_c[(t + 1) & 1];

        for (int b0 = 0; b0 < nv; b0 += 4) {
            int bc = (nv - b0) < 4 ? (nv - b0) : 4;
            if (t > 0) {
                for (int q = tid; q < bc * H_; q += 256)
                    hbuf[q] = __ldcg(&hsrc[b0 * H_ + q]);
            }
            __syncthreads();
            for (int bb = 0; bb < bc; bb++) {
                float ai = 0, af = 0, ag = 0, ao = 0;
                if (t > 0) {
                    const float* hp = &hbuf[bb * H_];
                    #pragma unroll
                    for (int i = 0; i < 16; i++) {
                        int kk = lane + 32 * i;
                        float h = hp[kk];
                        ai += w0[kk] * h; af += w1[kk] * h;
                        ag += w2[kk] * h; ao += w3[kk] * h;
                    }
                    ai = wred(ai); af = wred(af); ag = wred(ag); ao = wred(ao);
                }
                if (lane == 0) {
                    int b = b0 + bb;
                    const float* gx = &g_Gx[((size_t)t * B_ + b) * G4_];
                    float gi = ai + gx[j];
                    float gf = af + gx[H_ + j];
                    float gg = ag + gx[2 * H_ + j];
                    float go = ao + gx[3 * H_ + j];
                    float cp = (t > 0) ? csrc[b * H_ + j] : 0.f;  // own-warp write
                    float cn = sigf(gf) * cp + sigf(gi) * tanhf(gg);
                    cdst[b * H_ + j] = cn;
                    hdst[b * H_ + j] = sigf(go) * tanhf(cn);
                }
            }
            __syncthreads();
        }

        // grid barrier (monotonic counter, reset each replay by gxbwd)
        __threadfence();
        __syncthreads();
        if (tid == 0) {
            atomicAdd(&g_bar, 1);
            int target = NCTA_ * (t + 1);
            while (*(volatile int*)&g_bar < target) { }
        }
        __syncthreads();
    }

    // ---- final head: CTA 0 only (all h visible after last barrier) ----
    if (k != 0) return;
    const float* hf = g_h[P_ & 1];   // g_h[0]

    float* buf   = sm;               // [1024] staged z-source for one b
    float* ys    = sm + 1024;        // [512]
    float* red   = sm + 1024 + 512;  // [48]
    __syncthreads();

    int o0 = tid & 15,  i0 = tid >> 4;          // pair 0
    int o1 = (tid + 256) & 15, i1 = (tid + 256) >> 4;   // pair 1
    float acc0 = bfc[o0], acc1 = bfc[o1];

    for (int b = 0; b < nv; b++) {
        for (int q = tid; q < H_; q += 256) {
            buf[q]       = __ldcg(&hf[b * H_ + q]);
            buf[H_ + q]  = g_hb[b * H_ + q];
        }
        __syncthreads();
        #pragma unroll 8
        for (int jq = 0; jq < 32; jq++) {
            // z[i][j] = last[j%32][i*32 + j/32]; here j = jq*32 + b
            acc0 += buf[i0 * 32 + jq] * Wfc[o0 * (2 * H_) + jq * 32 + b];
            acc1 += buf[i1 * 32 + jq] * Wfc[o1 * (2 * H_) + jq * 32 + b];
        }
        __syncthreads();
    }
    ys[tid] = acc0;
    ys[tid + 256] = acc1;
    __syncthreads();

    float* mean_s = red; float* inv_s = red + 16; float* lse_s = red + 32;
    if (tid < O_) {
        float m = 0.f;
        for (int r = 0; r < B_; r++) m += ys[r * O_ + tid];
        m *= (1.f / B_);
        float v = 0.f;
        for (int r = 0; r < B_; r++) { float d = ys[r * O_ + tid] - m; v += d * d; }
        v *= (1.f / B_);
        mean_s[tid] = m;
        inv_s[tid] = 1.f / sqrtf(v + EPS_);
    }
    __syncthreads();

    float y0 = fmaxf(gamma[o0] * (ys[tid] - mean_s[o0]) * inv_s[o0] + beta[o0], 0.f);
    float y1 = fmaxf(gamma[o1] * (ys[tid + 256] - mean_s[o1]) * inv_s[o1] + beta[o1], 0.f);
    __syncthreads();
    ys[tid] = y0; ys[tid + 256] = y1;
    __syncthreads();

    if (tid < O_) {
        float mx = -3e38f;
        for (int r = 0; r < B_; r++) mx = fmaxf(mx, ys[r * O_ + tid]);
        float ss = 0.f;
        for (int r = 0; r < B_; r++) ss += expf(ys[r * O_ + tid] - mx);
        lse_s[tid] = logf(ss) + mx;
    }
    __syncthreads();

    out[i0 * O_ + o0] = ys[tid] - lse_s[o0];
    out[i1 * O_ + o1] = ys[tid + 256] - lse_s[o1];
}

// ---------------- launcher ----------------
extern "C" void kernel_launch(void* const* d_in, const int* in_sizes, int n_in,
                              void* d_out, int out_size)
{
    const int*  x    = (const int*)d_in[0];
    const int*  xm   = (const int*)d_in[1];
    const float* xf  = (const float*)d_in[2];
    const int*  lens = (const int*)d_in[3];
    const float* emb    = (const float*)d_in[6];
    const float* wattn  = (const float*)d_in[7];
    const float* battn  = (const float*)d_in[8];
    const float* Wih_f  = (const float*)d_in[9];
    const float* Whh_f  = (const float*)d_in[10];
    const float* bih_f  = (const float*)d_in[11];
    const float* bhh_f  = (const float*)d_in[12];
    const float* Wih_b  = (const float*)d_in[13];
    const float* bih_b  = (const float*)d_in[15];
    const float* bhh_b  = (const float*)d_in[16];
    const float* Wfc    = (const float*)d_in[17];
    const float* bfc    = (const float*)d_in[18];
    const float* gamma  = (const float*)d_in[19];
    const float* beta   = (const float*)d_in[20];
    float* out = (float*)d_out;

    const int K1_SMEM   = (S_ * H_ + H_ + 2 * S_) * 4 + 2 * S_ * 4;   // ~101 KB
    const int GX_SMEM   = P_ * 2 * D_ * 4;                             // 110592
    const int LSTM_SMEM = (32 * H_ + 4 * H_) * 4;                      // 73728
    cudaFuncSetAttribute(attn_rep_kernel,
                         cudaFuncAttributeMaxDynamicSharedMemorySize, K1_SMEM);
    cudaFuncSetAttribute(gxbwd_kernel,
                         cudaFuncAttributeMaxDynamicSharedMemorySize, GX_SMEM);
    cudaFuncSetAttribute(lstm_fused_kernel,
                         cudaFuncAttributeMaxDynamicSharedMemorySize, LSTM_SMEM);

    attn_rep_kernel<<<B_ * P_, 512, K1_SMEM>>>(x, xm, xf, lens, emb, wattn, battn);
    gxbwd_kernel<<<2 * NCTA_, 256, GX_SMEM>>>(lens, Wih_f, bih_f, bhh_f,
                                              Wih_b, bih_b, bhh_b);
    lstm_fused_kernel<<<NCTA_, 256, LSTM_SMEM>>>(lens, Whh_f, Wfc, bfc,
                                                 gamma, beta, out);
}